// round 5
// baseline (speedup 1.0000x reference)
#include <cuda_runtime.h>
#include <cstdint>

// Shapes fixed by the reference
#define B_   32
#define C_   256
#define HW_  4096
#define K_   32

#define THREADS 512
#define TILE_T  128
#define TILES_PER_BLOCK 8
#define CHUNK_T (TILE_T * TILES_PER_BLOCK)   // 1024 tokens per block
#define NBLOCKS (B_ * (HW_ / CHUNK_T))       // 128 blocks

// ---- shared memory layout (float offsets) ----
// XCM[256][132]: x tile channel-major (tf32-rounded). 132 % 32 == 4 makes both
// GEMM1 A-frag loads (banks 4q+g) and GEMM2 B-frag loads (banks 4g+q) hit 32
// distinct banks.
#define XCM_STRIDE 132
#define OFF_XCM 0
// WS[128][40]: softmax weights (tf32). 40 % 32 == 8 -> GEMM2 A-frag banks 8q+g
// cover 32 distinct banks.
#define WS_STRIDE 40
#define OFF_WS   (256 * XCM_STRIDE)                  // 33792
// CWF: codeword B fragments pre-packed in (kt,nt,lane)->{b0,b1} order; each
// per-mma B load is one conflict-free LDS.64.
#define OFF_CWF  (OFF_WS + TILE_T * WS_STRIDE)       // 38912
// XCS[128][36]: GEMM1 logits staging for the cross-warp softmax
#define XCS_STRIDE 36
#define OFF_XCS  (OFF_CWF + 8192)                    // 47104
#define OFF_XSQ  (OFF_XCS + TILE_T * XCS_STRIDE)     // 51712 (128 floats)
#define OFF_CSQ  (OFF_XSQ + TILE_T)                  // 32
#define OFF_SCL  (OFF_CSQ + K_)                      // 32
#define OFF_WSM  (OFF_SCL + K_)                      // 32
#define SMEM_FLOATS (OFF_WSM + K_)                   // 51936
#define SMEM_BYTES  (SMEM_FLOATS * 4)                // 207744 B

__device__ float g_wsum[B_ * K_];

// cvt.rna.tf32.f32 requires a .b32 destination -> "=r" constraint.
__device__ __forceinline__ uint32_t tf32_bits(float x) {
    uint32_t r; asm("cvt.rna.tf32.f32 %0, %1;" : "=r"(r) : "f"(x)); return r;
}
__device__ __forceinline__ float to_tf32(float x) {
    return __uint_as_float(tf32_bits(x));
}
__device__ __forceinline__ uint32_t f2u(float x) { return __float_as_uint(x); }

// m16n8k8 tf32 mma, D += A*B (C aliased to D)
__device__ __forceinline__ void mma_tf32(float c[4],
                                         uint32_t a0, uint32_t a1, uint32_t a2, uint32_t a3,
                                         uint32_t b0, uint32_t b1) {
    asm volatile(
        "mma.sync.aligned.m16n8k8.row.col.f32.tf32.tf32.f32 "
        "{%0,%1,%2,%3}, {%4,%5,%6,%7}, {%8,%9}, {%0,%1,%2,%3};"
        : "+f"(c[0]), "+f"(c[1]), "+f"(c[2]), "+f"(c[3])
        : "r"(a0), "r"(a1), "r"(a2), "r"(a3), "r"(b0), "r"(b1));
}

__global__ void enc_zero(float* __restrict__ out) {
    int i = blockIdx.x * 256 + threadIdx.x;   // grid covers exactly B*K*C = 262144
    out[i] = 0.f;
    if (i < B_ * K_) g_wsum[i] = 0.f;
}

__global__ void __launch_bounds__(THREADS, 1)
enc_main(const float* __restrict__ x, const float* __restrict__ cw,
         const float* __restrict__ scale, float* __restrict__ out)
{
    extern __shared__ float sm[];
    float* XCM = sm + OFF_XCM;
    float* WS  = sm + OFF_WS;
    float* CWF = sm + OFF_CWF;
    float* XCS = sm + OFF_XCS;
    float* XSQ = sm + OFF_XSQ;
    float* CSQ = sm + OFF_CSQ;
    float* SCL = sm + OFF_SCL;
    float* WSM = sm + OFF_WSM;

    const int t    = threadIdx.x;
    const int w    = t >> 5;        // warp 0..15
    const int lane = t & 31;
    const int q    = lane & 3;      // mma thread-in-group
    const int g    = lane >> 2;     // mma group id

    const int b     = blockIdx.x >> 2;
    const int chunk = blockIdx.x & 3;
    const float* xb = x + (size_t)b * (C_ * HW_);

    // ---------------- prologue: scale, c_sq (f32), packed codeword frags ----
    if (t < K_) { SCL[t] = scale[t]; WSM[t] = 0.f; }
    if (t < 256) {
        int code = t >> 3, p = t & 7;
        const float* cr = cw + code * C_ + p * 32;
        float s = 0.f;
        #pragma unroll
        for (int i = 0; i < 32; i++) s += cr[i] * cr[i];
        s += __shfl_xor_sync(0xffffffffu, s, 1);
        s += __shfl_xor_sync(0xffffffffu, s, 2);
        s += __shfl_xor_sync(0xffffffffu, s, 4);
        if (p == 0) CSQ[code] = s;
    }
    // B-frag packing: b0 = cw[nt*8 + lane/4][kt*8 + lane%4], b1 = +4 channels
    #pragma unroll
    for (int e = t; e < 4096; e += THREADS) {
        int kt = e >> 7, nt = (e >> 5) & 3, ln = e & 31;
        int code = nt * 8 + (ln >> 2);
        int ch   = kt * 8 + (ln & 3);
        float2 v;
        v.x = to_tf32(cw[code * C_ + ch]);
        v.y = to_tf32(cw[code * C_ + ch + 4]);
        *(float2*)(CWF + e * 2) = v;
    }

    // persistent GEMM2 accumulators: [mt codes16][ntl ch8][4]
    float acc[2][2][4];
    #pragma unroll
    for (int i = 0; i < 2; i++)
        #pragma unroll
        for (int j = 0; j < 2; j++)
            #pragma unroll
            for (int r = 0; r < 4; r++) acc[i][j][r] = 0.f;
    float wsum_acc[8];
    #pragma unroll
    for (int j = 0; j < 8; j++) wsum_acc[j] = 0.f;

    for (int tile = 0; tile < TILES_PER_BLOCK; tile++) {
        const int n0 = chunk * CHUNK_T + tile * TILE_T;

        __syncthreads();                 // prev GEMM2 done with XCM/WS
        if (t < TILE_T) XSQ[t] = 0.f;
        __syncthreads();

        // ---------- Phase A: gmem -> smem channel-major + f32 x_sq ---------
        {
            const float* src = xb + n0 + 4 * lane;
            float q0 = 0.f, q1 = 0.f, q2 = 0.f, q3 = 0.f;
            #pragma unroll
            for (int j = 0; j < 16; j++) {
                int c = j * 16 + w;      // warp loads a full 128-token row of channel c
                float4 v = *(const float4*)(src + (size_t)c * HW_);
                q0 += v.x * v.x; q1 += v.y * v.y;
                q2 += v.z * v.z; q3 += v.w * v.w;
                float4 tv;
                tv.x = to_tf32(v.x); tv.y = to_tf32(v.y);
                tv.z = to_tf32(v.z); tv.w = to_tf32(v.w);
                *(float4*)(XCM + c * XCM_STRIDE + 4 * lane) = tv;
            }
            atomicAdd(&XSQ[4 * lane + 0], q0);
            atomicAdd(&XSQ[4 * lane + 1], q1);
            atomicAdd(&XSQ[4 * lane + 2], q2);
            atomicAdd(&XSQ[4 * lane + 3], q3);
        }
        __syncthreads();

        // ---------- GEMM1: XC[128x32] = X * CW^T -------------------------
        {
            const int mt = w >> 1, nh = w & 1;
            float cfr[2][4] = {{0.f,0.f,0.f,0.f},{0.f,0.f,0.f,0.f}};
            const int tokA = mt * 16 + g;
            #pragma unroll 4
            for (int kt = 0; kt < 32; kt++) {
                const float* base = XCM + (kt * 8 + q) * XCM_STRIDE + tokA;
                uint32_t a0 = f2u(base[0]);
                uint32_t a1 = f2u(base[8]);
                uint32_t a2 = f2u(base[4 * XCM_STRIDE]);
                uint32_t a3 = f2u(base[4 * XCM_STRIDE + 8]);
                #pragma unroll
                for (int ntl = 0; ntl < 2; ntl++) {
                    int nt = nh * 2 + ntl;
                    float2 bv = *(const float2*)(CWF + ((kt * 4 + nt) * 32 + lane) * 2);
                    mma_tf32(cfr[ntl], a0, a1, a2, a3, f2u(bv.x), f2u(bv.y));
                }
            }
            #pragma unroll
            for (int ntl = 0; ntl < 2; ntl++) {
                int col = (nh * 2 + ntl) * 8 + q * 2;
                float* p0 = XCS + (mt * 16 + g) * XCS_STRIDE + col;
                *(float2*)p0 = make_float2(cfr[ntl][0], cfr[ntl][1]);
                *(float2*)(p0 + 8 * XCS_STRIDE) = make_float2(cfr[ntl][2], cfr[ntl][3]);
            }
        }
        __syncthreads();

        // ---------- softmax over K=32 per token (f32) ----------------------
        {
            const int row = t >> 2, qq = t & 3;       // 4 lanes per token
            float4 va = *(const float4*)(XCS + row * XCS_STRIDE + qq * 8);
            float4 vb = *(const float4*)(XCS + row * XCS_STRIDE + qq * 8 + 4);
            float xc8[8] = {va.x, va.y, va.z, va.w, vb.x, vb.y, vb.z, vb.w};
            float xsq = XSQ[row];
            float lg[8], mx = -1e30f;
            #pragma unroll
            for (int j = 0; j < 8; j++) {
                int k = qq * 8 + j;
                lg[j] = SCL[k] * (xsq - 2.f * xc8[j] + CSQ[k]);
                mx = fmaxf(mx, lg[j]);
            }
            mx = fmaxf(mx, __shfl_xor_sync(0xffffffffu, mx, 1));
            mx = fmaxf(mx, __shfl_xor_sync(0xffffffffu, mx, 2));
            float ex[8], sum = 0.f;
            #pragma unroll
            for (int j = 0; j < 8; j++) { ex[j] = __expf(lg[j] - mx); sum += ex[j]; }
            sum += __shfl_xor_sync(0xffffffffu, sum, 1);
            sum += __shfl_xor_sync(0xffffffffu, sum, 2);
            float inv = __fdividef(1.f, sum);
            float wv[8];
            #pragma unroll
            for (int j = 0; j < 8; j++) {
                float v = ex[j] * inv;
                wsum_acc[j] += v;
                wv[j] = to_tf32(v);
            }
            *(float4*)(WS + row * WS_STRIDE + qq * 8)     = make_float4(wv[0], wv[1], wv[2], wv[3]);
            *(float4*)(WS + row * WS_STRIDE + qq * 8 + 4) = make_float4(wv[4], wv[5], wv[6], wv[7]);
        }
        __syncthreads();

        // ---------- GEMM2: WX[32x256] += W^T * X (register-resident) -------
        {
            const int cb = w * 16;                    // this warp's channel strip
            #pragma unroll 4
            for (int kt = 0; kt < 16; kt++) {
                const float* wsb = WS + (kt * 8 + q) * WS_STRIDE;
                uint32_t aw[2][4];
                #pragma unroll
                for (int mt = 0; mt < 2; mt++) {
                    aw[mt][0] = f2u(wsb[mt * 16 + g]);
                    aw[mt][1] = f2u(wsb[mt * 16 + g + 8]);
                    aw[mt][2] = f2u(wsb[4 * WS_STRIDE + mt * 16 + g]);
                    aw[mt][3] = f2u(wsb[4 * WS_STRIDE + mt * 16 + g + 8]);
                }
                #pragma unroll
                for (int ntl = 0; ntl < 2; ntl++) {
                    const float* xp = XCM + (cb + ntl * 8 + g) * XCM_STRIDE + kt * 8;
                    uint32_t b0 = f2u(xp[q]);
                    uint32_t b1 = f2u(xp[q + 4]);
                    mma_tf32(acc[0][ntl], aw[0][0], aw[0][1], aw[0][2], aw[0][3], b0, b1);
                    mma_tf32(acc[1][ntl], aw[1][0], aw[1][1], aw[1][2], aw[1][3], b0, b1);
                }
            }
        }
    }

    // ---------------- epilogue: wsum reduce + wx scatter --------------------
    #pragma unroll
    for (int j = 0; j < 8; j++) {
        float v = wsum_acc[j];
        v += __shfl_xor_sync(0xffffffffu, v, 4);
        v += __shfl_xor_sync(0xffffffffu, v, 8);
        v += __shfl_xor_sync(0xffffffffu, v, 16);
        if (g == 0) atomicAdd(&WSM[q * 8 + j], v);
    }
    __syncthreads();
    if (t < K_) atomicAdd(&g_wsum[b * K_ + t], WSM[t]);

    float* ob = out + (size_t)b * (K_ * C_);
    #pragma unroll
    for (int mt = 0; mt < 2; mt++)
        #pragma unroll
        for (int ntl = 0; ntl < 2; ntl++) {
            int code = mt * 16 + g;
            int ch   = w * 16 + ntl * 8 + 2 * q;
            atomicAdd(ob + code * C_ + ch,           acc[mt][ntl][0]);
            atomicAdd(ob + code * C_ + ch + 1,       acc[mt][ntl][1]);
            atomicAdd(ob + (code + 8) * C_ + ch,     acc[mt][ntl][2]);
            atomicAdd(ob + (code + 8) * C_ + ch + 1, acc[mt][ntl][3]);
        }
}

__global__ void enc_finalize(float* __restrict__ out, const float* __restrict__ cw) {
    int i  = blockIdx.x * 256 + threadIdx.x;  // covers 262144
    int kc = i >> 8;                          // b*K + k
    int k  = kc & (K_ - 1);
    int c  = i & (C_ - 1);
    out[i] -= g_wsum[kc] * cw[k * C_ + c];
}

extern "C" void kernel_launch(void* const* d_in, const int* in_sizes, int n_in,
                              void* d_out, int out_size) {
    const float* x     = (const float*)d_in[0];
    const float* cwp   = (const float*)d_in[1];
    const float* scale = (const float*)d_in[2];
    float* out = (float*)d_out;

    // Idempotent, capture-safe (not a stream op); no static guard.
    cudaFuncSetAttribute(enc_main, cudaFuncAttributeMaxDynamicSharedMemorySize, SMEM_BYTES);

    enc_zero<<<(B_ * K_ * C_) / 256, 256>>>(out);
    enc_main<<<NBLOCKS, THREADS, SMEM_BYTES>>>(x, cwp, scale, out);
    enc_finalize<<<(B_ * K_ * C_) / 256, 256>>>(out, cwp);
}

// round 6
// speedup vs baseline: 1.0752x; 1.0752x over previous
#include <cuda_runtime.h>
#include <cstdint>

// Shapes fixed by the reference
#define B_   32
#define C_   256
#define HW_  4096
#define K_   32

#define THREADS 256
#define TILE_T  64
#define TILES_PER_BLOCK 8
#define CHUNK_T (TILE_T * TILES_PER_BLOCK)   // 512 tokens per block
#define NBLOCKS (B_ * (HW_ / CHUNK_T))       // 256 blocks -> 2 CTAs/SM

// ---- shared memory layout (float offsets) ----
// XCM[256][68]: x tile channel-major (raw f32; tf32 mma truncates). 68 % 32 == 4
// keeps both GEMM1 A-frag loads (banks 4q+g) and GEMM2 B-frag loads (banks
// 4g+q) conflict-free.
#define XCM_STRIDE 68
#define OFF_XCM 0
// WSX[64][40]: dual-use buffer. GEMM1 stores logits here (XCS role), softmax
// reads its own row then overwrites with tf32 weights (WS role) — reads
// strictly precede writes within the owning 4-lane group, so aliasing is safe.
// 40 % 32 == 8 -> GEMM2 A-frag banks 8q+g cover 32 distinct banks.
#define WSX_STRIDE 40
#define OFF_WSX  (256 * XCM_STRIDE)                  // 17408
// CWF: codeword B fragments pre-packed in (kt,nt,lane)->{b0,b1} order.
#define OFF_CWF  (OFF_WSX + TILE_T * WSX_STRIDE)     // 19968 (8192 floats)
#define OFF_XSQ  (OFF_CWF + 8192)                    // 28160 (64 floats)
#define OFF_CSQ  (OFF_XSQ + TILE_T)                  // 32
#define OFF_SCL  (OFF_CSQ + K_)                      // 32
#define OFF_WSM  (OFF_SCL + K_)                      // 32
#define SMEM_FLOATS (OFF_WSM + K_)                   // 28320
#define SMEM_BYTES  (SMEM_FLOATS * 4)                // 113280 B -> 2 CTAs/SM

__device__ float g_wsum[B_ * K_];

// cvt.rna.tf32.f32 requires a .b32 destination -> "=r" constraint.
__device__ __forceinline__ uint32_t tf32_bits(float x) {
    uint32_t r; asm("cvt.rna.tf32.f32 %0, %1;" : "=r"(r) : "f"(x)); return r;
}
__device__ __forceinline__ float to_tf32(float x) {
    return __uint_as_float(tf32_bits(x));
}
__device__ __forceinline__ uint32_t f2u(float x) { return __float_as_uint(x); }

// m16n8k8 tf32 mma, D += A*B (C aliased to D)
__device__ __forceinline__ void mma_tf32(float c[4],
                                         uint32_t a0, uint32_t a1, uint32_t a2, uint32_t a3,
                                         uint32_t b0, uint32_t b1) {
    asm volatile(
        "mma.sync.aligned.m16n8k8.row.col.f32.tf32.tf32.f32 "
        "{%0,%1,%2,%3}, {%4,%5,%6,%7}, {%8,%9}, {%0,%1,%2,%3};"
        : "+f"(c[0]), "+f"(c[1]), "+f"(c[2]), "+f"(c[3])
        : "r"(a0), "r"(a1), "r"(a2), "r"(a3), "r"(b0), "r"(b1));
}

__global__ void enc_zero(float* __restrict__ out) {
    int i = blockIdx.x * 256 + threadIdx.x;   // grid covers exactly B*K*C = 262144
    out[i] = 0.f;
    if (i < B_ * K_) g_wsum[i] = 0.f;
}

__global__ void __launch_bounds__(THREADS, 2)
enc_main(const float* __restrict__ x, const float* __restrict__ cw,
         const float* __restrict__ scale, float* __restrict__ out)
{
    extern __shared__ float sm[];
    float* XCM = sm + OFF_XCM;
    float* WSX = sm + OFF_WSX;
    float* CWF = sm + OFF_CWF;
    float* XSQ = sm + OFF_XSQ;
    float* CSQ = sm + OFF_CSQ;
    float* SCL = sm + OFF_SCL;
    float* WSM = sm + OFF_WSM;

    const int t    = threadIdx.x;
    const int w    = t >> 5;        // warp 0..7
    const int lane = t & 31;
    const int q    = lane & 3;      // mma thread-in-group
    const int g    = lane >> 2;     // mma group id

    const int b     = blockIdx.x >> 3;
    const int chunk = blockIdx.x & 7;
    const float* xb = x + (size_t)b * (C_ * HW_);

    // ---------------- prologue: scale, c_sq (f32), packed codeword frags ----
    if (t < K_) { SCL[t] = scale[t]; WSM[t] = 0.f; }
    {
        int code = t >> 3, p = t & 7;
        const float* cr = cw + code * C_ + p * 32;
        float s = 0.f;
        #pragma unroll
        for (int i = 0; i < 32; i++) s += cr[i] * cr[i];
        s += __shfl_xor_sync(0xffffffffu, s, 1);
        s += __shfl_xor_sync(0xffffffffu, s, 2);
        s += __shfl_xor_sync(0xffffffffu, s, 4);
        if (p == 0) CSQ[code] = s;
    }
    // B-frag packing: b0 = cw[nt*8 + lane/4][kt*8 + lane%4], b1 = +4 channels
    #pragma unroll
    for (int e = t; e < 4096; e += THREADS) {
        int kt = e >> 7, nt = (e >> 5) & 3, ln = e & 31;
        int code = nt * 8 + (ln >> 2);
        int ch   = kt * 8 + (ln & 3);
        float2 v;
        v.x = to_tf32(cw[code * C_ + ch]);
        v.y = to_tf32(cw[code * C_ + ch + 4]);
        *(float2*)(CWF + e * 2) = v;
    }

    // persistent GEMM2 accumulators: [mt codes16][ntl ch8][4]
    float acc[2][4][4];
    #pragma unroll
    for (int i = 0; i < 2; i++)
        #pragma unroll
        for (int j = 0; j < 4; j++)
            #pragma unroll
            for (int r = 0; r < 4; r++) acc[i][j][r] = 0.f;
    float wsum_acc[8];
    #pragma unroll
    for (int j = 0; j < 8; j++) wsum_acc[j] = 0.f;

    for (int tile = 0; tile < TILES_PER_BLOCK; tile++) {
        const int n0 = chunk * CHUNK_T + tile * TILE_T;

        __syncthreads();                 // prev GEMM2 done with XCM/WSX
        if (t < TILE_T) XSQ[t] = 0.f;
        __syncthreads();

        // ---------- Phase A: gmem -> smem channel-major + f32 x_sq ---------
        // Raw f32 into XCM: the tf32 mma truncates mantissas in HW, so no cvt
        // needed in this hot loop; x_sq uses full precision regardless.
        {
            const int ch16 = t >> 4;           // 0..15
            const int seg  = t & 15;           // 4-token segment
            const float* src = xb + n0 + 4 * seg;
            float q0 = 0.f, q1 = 0.f, q2 = 0.f, q3 = 0.f;
            #pragma unroll
            for (int j = 0; j < 16; j++) {
                int c = j * 16 + ch16;
                float4 v = *(const float4*)(src + (size_t)c * HW_);
                q0 += v.x * v.x; q1 += v.y * v.y;
                q2 += v.z * v.z; q3 += v.w * v.w;
                *(float4*)(XCM + c * XCM_STRIDE + 4 * seg) = v;
            }
            atomicAdd(&XSQ[4 * seg + 0], q0);
            atomicAdd(&XSQ[4 * seg + 1], q1);
            atomicAdd(&XSQ[4 * seg + 2], q2);
            atomicAdd(&XSQ[4 * seg + 3], q3);
        }
        __syncthreads();

        // ---------- GEMM1: XC[64x32] = X * CW^T ----------------------------
        {
            const int mt = w >> 1, nh = w & 1;   // mt 0..3, nh 0..1
            float cfr[2][4] = {{0.f,0.f,0.f,0.f},{0.f,0.f,0.f,0.f}};
            const int tokA = mt * 16 + g;
            #pragma unroll 4
            for (int kt = 0; kt < 32; kt++) {
                const float* base = XCM + (kt * 8 + q) * XCM_STRIDE + tokA;
                uint32_t a0 = f2u(base[0]);
                uint32_t a1 = f2u(base[8]);
                uint32_t a2 = f2u(base[4 * XCM_STRIDE]);
                uint32_t a3 = f2u(base[4 * XCM_STRIDE + 8]);
                #pragma unroll
                for (int ntl = 0; ntl < 2; ntl++) {
                    int nt = nh * 2 + ntl;
                    float2 bv = *(const float2*)(CWF + ((kt * 4 + nt) * 32 + lane) * 2);
                    mma_tf32(cfr[ntl], a0, a1, a2, a3, f2u(bv.x), f2u(bv.y));
                }
            }
            #pragma unroll
            for (int ntl = 0; ntl < 2; ntl++) {
                int col = (nh * 2 + ntl) * 8 + q * 2;
                float* p0 = WSX + (mt * 16 + g) * WSX_STRIDE + col;
                *(float2*)p0 = make_float2(cfr[ntl][0], cfr[ntl][1]);
                *(float2*)(p0 + 8 * WSX_STRIDE) = make_float2(cfr[ntl][2], cfr[ntl][3]);
            }
        }
        __syncthreads();

        // ---------- softmax over K=32 per token (f32, in-place in WSX) -----
        {
            const int row = t >> 2, qq = t & 3;       // 4 lanes per token
            float4 va = *(const float4*)(WSX + row * WSX_STRIDE + qq * 8);
            float4 vb = *(const float4*)(WSX + row * WSX_STRIDE + qq * 8 + 4);
            float xc8[8] = {va.x, va.y, va.z, va.w, vb.x, vb.y, vb.z, vb.w};
            float xsq = XSQ[row];
            float lg[8], mx = -1e30f;
            #pragma unroll
            for (int j = 0; j < 8; j++) {
                int k = qq * 8 + j;
                lg[j] = SCL[k] * (xsq - 2.f * xc8[j] + CSQ[k]);
                mx = fmaxf(mx, lg[j]);
            }
            mx = fmaxf(mx, __shfl_xor_sync(0xffffffffu, mx, 1));
            mx = fmaxf(mx, __shfl_xor_sync(0xffffffffu, mx, 2));
            float ex[8], sum = 0.f;
            #pragma unroll
            for (int j = 0; j < 8; j++) { ex[j] = __expf(lg[j] - mx); sum += ex[j]; }
            sum += __shfl_xor_sync(0xffffffffu, sum, 1);
            sum += __shfl_xor_sync(0xffffffffu, sum, 2);
            float inv = __fdividef(1.f, sum);
            float wv[8];
            #pragma unroll
            for (int j = 0; j < 8; j++) {
                float v = ex[j] * inv;
                wsum_acc[j] += v;
                wv[j] = to_tf32(v);
            }
            *(float4*)(WSX + row * WSX_STRIDE + qq * 8)     = make_float4(wv[0], wv[1], wv[2], wv[3]);
            *(float4*)(WSX + row * WSX_STRIDE + qq * 8 + 4) = make_float4(wv[4], wv[5], wv[6], wv[7]);
        }
        __syncthreads();

        // ---------- GEMM2: WX[32x256] += W^T * X (register-resident) -------
        {
            const int cb = w * 32;                    // this warp's 32-channel strip
            #pragma unroll
            for (int kt = 0; kt < 8; kt++) {
                const float* wsb = WSX + (kt * 8 + q) * WSX_STRIDE;
                uint32_t aw[2][4];
                #pragma unroll
                for (int mt = 0; mt < 2; mt++) {
                    aw[mt][0] = f2u(wsb[mt * 16 + g]);
                    aw[mt][1] = f2u(wsb[mt * 16 + g + 8]);
                    aw[mt][2] = f2u(wsb[4 * WSX_STRIDE + mt * 16 + g]);
                    aw[mt][3] = f2u(wsb[4 * WSX_STRIDE + mt * 16 + g + 8]);
                }
                #pragma unroll
                for (int ntl = 0; ntl < 4; ntl++) {
                    const float* xp = XCM + (cb + ntl * 8 + g) * XCM_STRIDE + kt * 8;
                    uint32_t b0 = f2u(xp[q]);
                    uint32_t b1 = f2u(xp[q + 4]);
                    mma_tf32(acc[0][ntl], aw[0][0], aw[0][1], aw[0][2], aw[0][3], b0, b1);
                    mma_tf32(acc[1][ntl], aw[1][0], aw[1][1], aw[1][2], aw[1][3], b0, b1);
                }
            }
        }
    }

    // ---------------- epilogue: wsum reduce + wx scatter --------------------
    #pragma unroll
    for (int j = 0; j < 8; j++) {
        float v = wsum_acc[j];
        v += __shfl_xor_sync(0xffffffffu, v, 4);
        v += __shfl_xor_sync(0xffffffffu, v, 8);
        v += __shfl_xor_sync(0xffffffffu, v, 16);
        if (g == 0) atomicAdd(&WSM[q * 8 + j], v);
    }
    __syncthreads();
    if (t < K_) atomicAdd(&g_wsum[b * K_ + t], WSM[t]);

    float* ob = out + (size_t)b * (K_ * C_);
    #pragma unroll
    for (int mt = 0; mt < 2; mt++)
        #pragma unroll
        for (int ntl = 0; ntl < 4; ntl++) {
            int code = mt * 16 + g;
            int ch   = w * 32 + ntl * 8 + 2 * q;
            atomicAdd(ob + code * C_ + ch,           acc[mt][ntl][0]);
            atomicAdd(ob + code * C_ + ch + 1,       acc[mt][ntl][1]);
            atomicAdd(ob + (code + 8) * C_ + ch,     acc[mt][ntl][2]);
            atomicAdd(ob + (code + 8) * C_ + ch + 1, acc[mt][ntl][3]);
        }
}

__global__ void enc_finalize(float* __restrict__ out, const float* __restrict__ cw) {
    int i  = blockIdx.x * 256 + threadIdx.x;  // covers 262144
    int kc = i >> 8;                          // b*K + k
    int k  = kc & (K_ - 1);
    int c  = i & (C_ - 1);
    out[i] -= g_wsum[kc] * cw[k * C_ + c];
}

extern "C" void kernel_launch(void* const* d_in, const int* in_sizes, int n_in,
                              void* d_out, int out_size) {
    const float* x     = (const float*)d_in[0];
    const float* cwp   = (const float*)d_in[1];
    const float* scale = (const float*)d_in[2];
    float* out = (float*)d_out;

    // Idempotent, capture-safe (not a stream op); no static guard.
    cudaFuncSetAttribute(enc_main, cudaFuncAttributeMaxDynamicSharedMemorySize, SMEM_BYTES);

    enc_zero<<<(B_ * K_ * C_) / 256, 256>>>(out);
    enc_main<<<NBLOCKS, THREADS, SMEM_BYTES>>>(x, cwp, scale, out);
    enc_finalize<<<(B_ * K_ * C_) / 256, 256>>>(out, cwp);
}